// round 13
// baseline (speedup 1.0000x reference)
#include <cuda_runtime.h>
#include <cuda_bf16.h>
#include <math.h>
#include <stdint.h>

// ---------------- problem constants ----------------
#define SEQ   1024
#define TLEN  512
#define NG    1024
#define HTOT  16384
#define D_LOC 512
#define D_TIM 32
#define D_CLU 64
#define D_UID 64
#define HID   512
#define INP   608            // D_LOC + D_CLU + D_TIM
#define THID  1536           // 3*HID
#define NLOC  50000
#define OUTD  1088           // 2*HID + D_UID

// GRU persistent kernel: CTAs 0..31 scan; CTAs 32..147 do hist pipeline + convert
#define GRU_CTAS 32
#define GRU_GRID 148
#define NHELP (GRU_GRID - GRU_CTAS)      // 116 helper CTAs
#define GRU_UPC  16                      // hidden units per CTA
#define GRU_ROWS 48                      // 3 * GRU_UPC w_hh rows per CTA
#define GRU_THREADS 512                  // 16 warps
#define GRU_RPW  3                       // rows per warp
#define GRU_SMEM (GRU_ROWS * HID * 4 + GRU_ROWS * 4 * 2)   // ws + rowsum + bias

// final GEMM (bf16 tensor) config
#define FG_BM 128
#define FG_BN 128
#define FG_BK 32
#define FG_PAD 40            // halves per smem row (80B stride, conflict-free LDSM)
#define FG_NK (OUTD / FG_BK) // 34

// ---------------- device scratch ----------------
__device__ float g_x[SEQ * INP];
__device__ float g_gx[SEQ * THID];
__device__ float g_hfeat[NG * INP];
__device__ float g_hist[NG * HID];
__device__ float g_hbuf[2][HID];
__device__ float g_q[TLEN * HID];
__device__ float g_attn[TLEN * NG];
__device__ float g_ctx[TLEN * HID];
__device__ __nv_bfloat16 g_out_bf[TLEN * OUTD];
__device__ __nv_bfloat16 g_wf_bf[(size_t)NLOC * OUTD];
__device__ int   g_off[NG];
__device__ int   g_bars[2];
__device__ int   g_help;

// ---------------- offsets (prefix sum of history_count) + barrier reset ----------------
__global__ void offsets_kernel(const int* __restrict__ cnt) {
    __shared__ int s[NG];
    int tid = threadIdx.x;
    s[tid] = cnt[tid];
    __syncthreads();
    for (int d = 1; d < NG; d <<= 1) {
        int v = (tid >= d) ? s[tid - d] : 0;
        __syncthreads();
        s[tid] += v;
        __syncthreads();
    }
    g_off[tid] = s[tid] - cnt[tid];
    if (tid < 2) g_bars[tid] = 0;
    if (tid == 2) g_help = 0;
}

// ---------------- x features ----------------
__global__ void build_x_kernel(const int* __restrict__ loc, const int* __restrict__ clu,
                               const int* __restrict__ tim,
                               const float* __restrict__ emb_loc, const float* __restrict__ emb_clu,
                               const float* __restrict__ emb_tim) {
    int s = blockIdx.x;
    int tid = threadIdx.x;
    int l = loc[s], c = clu[s], t = tim[s];
    float* dst = g_x + (size_t)s * INP;
    for (int d = tid; d < D_LOC; d += blockDim.x) dst[d] = emb_loc[(size_t)l * D_LOC + d];
    for (int d = tid; d < D_CLU; d += blockDim.x) dst[D_LOC + d] = emb_clu[(size_t)c * D_CLU + d];
    for (int d = tid; d < D_TIM; d += blockDim.x) dst[D_LOC + D_CLU + d] = emb_tim[(size_t)t * D_TIM + d];
}

// ---------------- fp32 GEMM 64x64x16, C = A[M,K] * B[N,K]^T (+bias)(+tanh) ----------------
__global__ __launch_bounds__(128)
void gemm_nt64(const float* __restrict__ A, const float* __restrict__ B, float* __restrict__ C,
               int M, int N, int K, const float* __restrict__ bias, int act) {
    __shared__ float As[16][68];
    __shared__ float Bs[16][68];
    int m0 = blockIdx.y * 64, n0 = blockIdx.x * 64;
    int tid = threadIdx.x;
    int tx = tid & 15, ty = tid >> 4;
    float c[8][4];
#pragma unroll
    for (int i = 0; i < 8; i++)
#pragma unroll
        for (int j = 0; j < 4; j++) c[i][j] = 0.0f;

    for (int k0 = 0; k0 < K; k0 += 16) {
#pragma unroll
        for (int h = 0; h < 2; h++) {
            int cidx = tid + h * 128;
            int r = cidx >> 2, k4 = (cidx & 3) * 4;
            float4 av = *(const float4*)(A + (size_t)(m0 + r) * K + k0 + k4);
            As[k4 + 0][r] = av.x; As[k4 + 1][r] = av.y; As[k4 + 2][r] = av.z; As[k4 + 3][r] = av.w;
            float4 bv = *(const float4*)(B + (size_t)(n0 + r) * K + k0 + k4);
            Bs[k4 + 0][r] = bv.x; Bs[k4 + 1][r] = bv.y; Bs[k4 + 2][r] = bv.z; Bs[k4 + 3][r] = bv.w;
        }
        __syncthreads();
#pragma unroll
        for (int k = 0; k < 16; k++) {
            float a[8], b[4];
            *(float4*)&a[0] = *(const float4*)&As[k][ty * 8];
            *(float4*)&a[4] = *(const float4*)&As[k][ty * 8 + 4];
            *(float4*)&b[0] = *(const float4*)&Bs[k][tx * 4];
#pragma unroll
            for (int i = 0; i < 8; i++)
#pragma unroll
                for (int j = 0; j < 4; j++) c[i][j] = fmaf(a[i], b[j], c[i][j]);
        }
        __syncthreads();
    }
#pragma unroll
    for (int i = 0; i < 8; i++) {
        int m = m0 + ty * 8 + i;
#pragma unroll
        for (int j = 0; j < 4; j++) {
            int n = n0 + tx * 4 + j;
            float v = c[i][j];
            if (bias) v += bias[n];
            if (act == 1) v = tanhf(v);
            C[(size_t)m * N + n] = v;
        }
    }
}

// ---------------- fp32 GEMM 64x64x16, C = A[M,K] * B[K,N] ----------------
__global__ __launch_bounds__(128)
void gemm_nn64(const float* __restrict__ A, const float* __restrict__ B, float* __restrict__ C,
               int M, int N, int K) {
    __shared__ float As[16][68];
    __shared__ float Bs[16][68];
    int m0 = blockIdx.y * 64, n0 = blockIdx.x * 64;
    int tid = threadIdx.x;
    int tx = tid & 15, ty = tid >> 4;
    float c[8][4];
#pragma unroll
    for (int i = 0; i < 8; i++)
#pragma unroll
        for (int j = 0; j < 4; j++) c[i][j] = 0.0f;

    for (int k0 = 0; k0 < K; k0 += 16) {
#pragma unroll
        for (int h = 0; h < 2; h++) {
            int cidx = tid + h * 128;
            int r = cidx >> 2, k4 = (cidx & 3) * 4;
            float4 av = *(const float4*)(A + (size_t)(m0 + r) * K + k0 + k4);
            As[k4 + 0][r] = av.x; As[k4 + 1][r] = av.y; As[k4 + 2][r] = av.z; As[k4 + 3][r] = av.w;
            int kr = cidx >> 4, c4 = (cidx & 15) * 4;
            *(float4*)&Bs[kr][c4] = *(const float4*)(B + (size_t)(k0 + kr) * N + n0 + c4);
        }
        __syncthreads();
#pragma unroll
        for (int k = 0; k < 16; k++) {
            float a[8], b[4];
            *(float4*)&a[0] = *(const float4*)&As[k][ty * 8];
            *(float4*)&a[4] = *(const float4*)&As[k][ty * 8 + 4];
            *(float4*)&b[0] = *(const float4*)&Bs[k][tx * 4];
#pragma unroll
            for (int i = 0; i < 8; i++)
#pragma unroll
                for (int j = 0; j < 4; j++) c[i][j] = fmaf(a[i], b[j], c[i][j]);
        }
        __syncthreads();
    }
#pragma unroll
    for (int i = 0; i < 8; i++) {
        int m = m0 + ty * 8 + i;
#pragma unroll
        for (int j = 0; j < 4; j++)
            C[(size_t)m * N + n0 + tx * 4 + j] = c[i][j];
    }
}

// ---------------- persistent GRU scan + overlapped hist pipeline + weight conversion ----
// CTAs 0..31: exact round-12 scan (ping-pong barrier counters).
// CTAs 32..147 (helpers), during the scan:
//   phase 1: hist_feat for 1024 groups (grid-stride)
//   helper-only barrier (counter + volatile poll -- proven idiom)
//   phase 2: hist = tanh(hfeat @ fc_attn_w^T + b), 128 64x64 tiles (grid-stride)
//   phase 3: fc_final_w fp32->bf16 conversion
__global__ void __launch_bounds__(GRU_THREADS, 1)
gru_kernel(const float* __restrict__ gx, const float* __restrict__ w_hh,
           const float* __restrict__ b_hh, float* __restrict__ q,
           const float* __restrict__ wf,
           const int* __restrict__ hloc, const int* __restrict__ hclu,
           const int* __restrict__ htim, const int* __restrict__ hcnt,
           const float* __restrict__ emb_loc, const float* __restrict__ emb_clu,
           const float* __restrict__ emb_tim,
           const float* __restrict__ fc_attn_w, const float* __restrict__ fc_attn_b) {
    extern __shared__ float sm[];
    int b = blockIdx.x;
    int tid = threadIdx.x;

    if (b >= GRU_CTAS) {
        int hb = b - GRU_CTAS;                       // 0..115

        // ---- phase 1: history features ----
        for (int g = hb; g < NG; g += NHELP) {
            int off = g_off[g];
            int cnt = hcnt[g];
            float inv = 1.0f / (float)cnt;
            float* dst = g_hfeat + (size_t)g * INP;
            for (int d = tid; d < D_LOC; d += GRU_THREADS) {
                float s = 0.0f;
                for (int i = 0; i < cnt; i++)
                    s += emb_loc[(size_t)hloc[off + i] * D_LOC + d];
                dst[d] = s * inv;
            }
            for (int d = tid; d < D_CLU; d += GRU_THREADS) {
                float s = 0.0f;
                for (int i = 0; i < cnt; i++)
                    s += emb_clu[(size_t)hclu[off + i] * D_CLU + d];
                dst[D_LOC + d] = s * inv;
            }
            int t0 = htim[off];
            for (int d = tid; d < D_TIM; d += GRU_THREADS)
                dst[D_LOC + D_CLU + d] = emb_tim[(size_t)t0 * D_TIM + d];
        }

        // ---- helper-only barrier (proven counter mechanism) ----
        __threadfence();
        __syncthreads();
        if (tid == 0) {
            atomicAdd(&g_help, 1);
            volatile int* vh = &g_help;
            while (*vh < NHELP) { }
            __threadfence();
        }
        __syncthreads();

        // ---- phase 2: hist GEMM tiles (64x64, K=608), loaders tid<256, compute tid<128 ----
        float (*As)[68] = (float (*)[68])sm;
        float (*Bs)[68] = (float (*)[68])(sm + 16 * 68);
        for (int tl = hb; tl < (HID / 64) * (NG / 64); tl += NHELP) {
            int n0 = (tl & 7) * 64;              // HID/64 = 8 tiles across
            int m0 = (tl >> 3) * 64;
            int tx = tid & 15, ty = (tid >> 4) & 7;
            float c[8][4];
#pragma unroll
            for (int i = 0; i < 8; i++)
#pragma unroll
                for (int j = 0; j < 4; j++) c[i][j] = 0.0f;
            for (int k0 = 0; k0 < INP; k0 += 16) {
                if (tid < 256) {
                    int r = tid >> 2, k4 = (tid & 3) * 4;
                    float4 av = *(const float4*)(g_hfeat + (size_t)(m0 + r) * INP + k0 + k4);
                    As[k4 + 0][r] = av.x; As[k4 + 1][r] = av.y; As[k4 + 2][r] = av.z; As[k4 + 3][r] = av.w;
                    float4 bv = *(const float4*)(fc_attn_w + (size_t)(n0 + r) * INP + k0 + k4);
                    Bs[k4 + 0][r] = bv.x; Bs[k4 + 1][r] = bv.y; Bs[k4 + 2][r] = bv.z; Bs[k4 + 3][r] = bv.w;
                }
                __syncthreads();
                if (tid < 128) {
#pragma unroll
                    for (int k = 0; k < 16; k++) {
                        float a[8], bb_[4];
                        *(float4*)&a[0] = *(const float4*)&As[k][ty * 8];
                        *(float4*)&a[4] = *(const float4*)&As[k][ty * 8 + 4];
                        *(float4*)&bb_[0] = *(const float4*)&Bs[k][tx * 4];
#pragma unroll
                        for (int i = 0; i < 8; i++)
#pragma unroll
                            for (int j = 0; j < 4; j++) c[i][j] = fmaf(a[i], bb_[j], c[i][j]);
                    }
                }
                __syncthreads();
            }
            if (tid < 128) {
#pragma unroll
                for (int i = 0; i < 8; i++) {
                    int m = m0 + ty * 8 + i;
#pragma unroll
                    for (int j = 0; j < 4; j++) {
                        int n = n0 + tx * 4 + j;
                        g_hist[(size_t)m * HID + n] = tanhf(c[i][j] + fc_attn_b[n]);
                    }
                }
            }
        }

        // ---- phase 3: fc_final_w conversion ----
        size_t n4 = (size_t)NLOC * OUTD / 4;
        const float4* src = (const float4*)wf;
        uint2* dst = (uint2*)g_wf_bf;
        size_t stride = (size_t)NHELP * GRU_THREADS;
        for (size_t i = (size_t)hb * GRU_THREADS + tid; i < n4; i += stride) {
            float4 v = src[i];
            __nv_bfloat162 lo = __floats2bfloat162_rn(v.x, v.y);
            __nv_bfloat162 hi = __floats2bfloat162_rn(v.z, v.w);
            uint2 o;
            o.x = *(unsigned int*)&lo;
            o.y = *(unsigned int*)&hi;
            dst[i] = o;
        }
        return;
    }

    // ---------------- scan CTAs (byte-identical to round 12) ----------------
    float* ws     = sm;                       // [48][512]
    float* rowsum = sm + GRU_ROWS * HID;      // [48]
    float* bb     = rowsum + GRU_ROWS;        // [48]
    int wid = tid >> 5, lane = tid & 31;
    int j0 = b * GRU_UPC;

    const float4* w4 = (const float4*)w_hh;
    float4* ws4 = (float4*)ws;
    for (int i4 = tid; i4 < GRU_ROWS * (HID / 4); i4 += GRU_THREADS) {
        int row = i4 >> 7, pos = i4 & 127;
        int g = row >> 4, u = row & 15;
        int grow = g * HID + j0 + u;
        ws4[i4] = w4[(size_t)grow * (HID / 4) + pos];
    }
    if (tid < GRU_ROWS) {
        int g = tid >> 4, u = tid & 15;
        bb[tid] = b_hh[g * HID + j0 + u];
    }
    __syncthreads();

    for (int t = 0; t < SEQ; t++) {
        const float* hr = g_hbuf[t & 1];

        float gxr = 0.f, gxz = 0.f, gxn = 0.f, hold = 0.f;
        if (tid < GRU_UPC) {
            const float* gxt = gx + (size_t)t * THID + j0 + tid;
            gxr = __ldcg(gxt);
            gxz = __ldcg(gxt + HID);
            gxn = __ldcg(gxt + 2 * HID);
            hold = (t == 0) ? 0.0f : __ldcg(&hr[j0 + tid]);
        }

        float4 hv[4];
#pragma unroll
        for (int c = 0; c < 4; c++)
            hv[c] = (t == 0) ? make_float4(0.f, 0.f, 0.f, 0.f)
                             : __ldcg((const float4*)&hr[lane * 4 + 128 * c]);

#pragma unroll
        for (int rr = 0; rr < GRU_RPW; rr++) {
            int row = wid * GRU_RPW + rr;
            const float4* wr = (const float4*)(ws + row * HID);
            float acc = 0.0f;
#pragma unroll
            for (int c = 0; c < 4; c++) {
                float4 wv = wr[lane + 32 * c];
                acc += wv.x * hv[c].x + wv.y * hv[c].y + wv.z * hv[c].z + wv.w * hv[c].w;
            }
#pragma unroll
            for (int o = 16; o; o >>= 1) acc += __shfl_xor_sync(0xffffffffu, acc, o);
            if (lane == 0) rowsum[row] = acc + bb[row];
        }
        __syncthreads();

        if (tid < GRU_UPC) {
            float r = 1.0f / (1.0f + expf(-(gxr + rowsum[tid])));
            float z = 1.0f / (1.0f + expf(-(gxz + rowsum[GRU_UPC + tid])));
            float n = tanhf(gxn + r * rowsum[2 * GRU_UPC + tid]);
            float hnew = (1.0f - z) * n + z * hold;
            __stcg(&g_hbuf[(t + 1) & 1][j0 + tid], hnew);
            if (t >= SEQ - TLEN)
                q[(size_t)(t - (SEQ - TLEN)) * HID + j0 + tid] = hnew;
            __threadfence();
        }
        __syncthreads();

        if (tid == 0) {
            int c = t & 1;
            atomicAdd(&g_bars[c], 1);
            volatile int* vb = &g_bars[c];
            int target = GRU_CTAS * ((t >> 1) + 1);
            while (*vb < target) { }
            __threadfence();
        }
        __syncthreads();
    }
}

// ---------------- row softmax (attn) ----------------
__global__ void softmax_kernel(float* __restrict__ a, int n) {
    float* row = a + (size_t)blockIdx.x * n;
    __shared__ float red[256];
    int tid = threadIdx.x;
    float m = -INFINITY;
    for (int i = tid; i < n; i += 256) m = fmaxf(m, row[i]);
    red[tid] = m; __syncthreads();
    for (int o = 128; o; o >>= 1) { if (tid < o) red[tid] = fmaxf(red[tid], red[tid + o]); __syncthreads(); }
    m = red[0]; __syncthreads();
    float s = 0.0f;
    for (int i = tid; i < n; i += 256) s += expf(row[i] - m);
    red[tid] = s; __syncthreads();
    for (int o = 128; o; o >>= 1) { if (tid < o) red[tid] += red[tid + o]; __syncthreads(); }
    float inv = 1.0f / red[0];
    for (int i = tid; i < n; i += 256) row[i] = expf(row[i] - m) * inv;
}

// ---------------- concat(q, context, uid_emb) -> bf16 ----------------
__global__ void build_out_kernel(const float* __restrict__ emb_uid, const int* __restrict__ uid) {
    int t = blockIdx.x;
    int tid = threadIdx.x;
    int u = uid[0];
    __nv_bfloat16* dst = g_out_bf + (size_t)t * OUTD;
    for (int d = tid; d < HID; d += blockDim.x) dst[d] = __float2bfloat16(g_q[(size_t)t * HID + d]);
    for (int d = tid; d < HID; d += blockDim.x) dst[HID + d] = __float2bfloat16(g_ctx[(size_t)t * HID + d]);
    for (int d = tid; d < D_UID; d += blockDim.x) dst[2 * HID + d] = __float2bfloat16(emb_uid[(size_t)u * D_UID + d]);
}

// ---------------- bf16 tensor-core final GEMM: C[512,50000] = A @ B^T + bias ----------------
__device__ __forceinline__ void ldsm_x4(unsigned& a0, unsigned& a1, unsigned& a2, unsigned& a3, uint32_t addr) {
    asm volatile("ldmatrix.sync.aligned.m8n8.x4.shared.b16 {%0,%1,%2,%3}, [%4];"
                 : "=r"(a0), "=r"(a1), "=r"(a2), "=r"(a3) : "r"(addr));
}
__device__ __forceinline__ void ldsm_x2(unsigned& b0, unsigned& b1, uint32_t addr) {
    asm volatile("ldmatrix.sync.aligned.m8n8.x2.shared.b16 {%0,%1}, [%2];"
                 : "=r"(b0), "=r"(b1) : "r"(addr));
}
__device__ __forceinline__ void mma16816(float& c0, float& c1, float& c2, float& c3,
                                         unsigned a0, unsigned a1, unsigned a2, unsigned a3,
                                         unsigned b0, unsigned b1) {
    asm volatile("mma.sync.aligned.m16n8k16.row.col.f32.bf16.bf16.f32 "
                 "{%0,%1,%2,%3}, {%4,%5,%6,%7}, {%8,%9}, {%0,%1,%2,%3};"
                 : "+f"(c0), "+f"(c1), "+f"(c2), "+f"(c3)
                 : "r"(a0), "r"(a1), "r"(a2), "r"(a3), "r"(b0), "r"(b1));
}
__device__ __forceinline__ void cp16(uint32_t saddr, const void* gaddr) {
    asm volatile("cp.async.cg.shared.global [%0], [%1], 16;" :: "r"(saddr), "l"(gaddr));
}
__device__ __forceinline__ void cp16_pred(uint32_t saddr, const void* gaddr, bool p) {
    int sz = p ? 16 : 0;
    asm volatile("cp.async.cg.shared.global [%0], [%1], 16, %2;" :: "r"(saddr), "l"(gaddr), "r"(sz));
}

__global__ __launch_bounds__(256)
void gemm_final_bf16(const __nv_bfloat16* __restrict__ A, const __nv_bfloat16* __restrict__ B,
                     float* __restrict__ C, const float* __restrict__ bias) {
    __shared__ __nv_bfloat16 As[2][FG_BM * FG_PAD];
    __shared__ __nv_bfloat16 Bs[2][FG_BN * FG_PAD];
    const int K = OUTD, N = NLOC;
    int n0 = blockIdx.x * FG_BN, m0 = blockIdx.y * FG_BM;
    int tid = threadIdx.x, lane = tid & 31, warp = tid >> 5;
    int wm = warp >> 2, wn = warp & 3;

    float acc[4][4][4];
#pragma unroll
    for (int mt = 0; mt < 4; mt++)
#pragma unroll
        for (int nt = 0; nt < 4; nt++)
#pragma unroll
            for (int i = 0; i < 4; i++) acc[mt][nt][i] = 0.0f;

    uint32_t as0 = (uint32_t)__cvta_generic_to_shared(&As[0][0]);
    uint32_t as1 = (uint32_t)__cvta_generic_to_shared(&As[1][0]);
    uint32_t bs0 = (uint32_t)__cvta_generic_to_shared(&Bs[0][0]);
    uint32_t bs1 = (uint32_t)__cvta_generic_to_shared(&Bs[1][0]);

    int lrow = tid >> 2;
    int lcol = (tid & 3) * 8;

    auto load_tile = [&](int buf, int kt) {
        int k0 = kt * FG_BK;
        uint32_t ab = buf ? as1 : as0;
        uint32_t bb_ = buf ? bs1 : bs0;
#pragma unroll
        for (int h = 0; h < 2; h++) {
            int r = lrow + h * 64;
            cp16(ab + (r * FG_PAD + lcol) * 2, A + (size_t)(m0 + r) * K + k0 + lcol);
            int n = n0 + r;
            bool ok = n < N;
            const __nv_bfloat16* src = B + (size_t)(ok ? n : 0) * K + k0 + lcol;
            cp16_pred(bb_ + (r * FG_PAD + lcol) * 2, src, ok);
        }
    };

    load_tile(0, 0);
    asm volatile("cp.async.commit_group;");

    int l15 = lane & 15;
    int lkA = (lane >> 4) * 8;
    int l7 = lane & 7;
    int lkB = ((lane >> 3) & 1) * 8;

    for (int kt = 0; kt < FG_NK; kt++) {
        if (kt + 1 < FG_NK) {
            load_tile((kt + 1) & 1, kt + 1);
            asm volatile("cp.async.commit_group;");
            asm volatile("cp.async.wait_group 1;");
        } else {
            asm volatile("cp.async.wait_group 0;");
        }
        __syncthreads();
        int buf = kt & 1;
        uint32_t ab = buf ? as1 : as0;
        uint32_t bb_ = buf ? bs1 : bs0;
#pragma unroll
        for (int kk = 0; kk < FG_BK; kk += 16) {
            unsigned a[4][4], b[4][2];
#pragma unroll
            for (int mt = 0; mt < 4; mt++) {
                int row = wm * 64 + mt * 16 + l15;
                ldsm_x4(a[mt][0], a[mt][1], a[mt][2], a[mt][3],
                        ab + (row * FG_PAD + kk + lkA) * 2);
            }
#pragma unroll
            for (int nt = 0; nt < 4; nt++) {
                int row = wn * 32 + nt * 8 + l7;
                ldsm_x2(b[nt][0], b[nt][1],
                        bb_ + (row * FG_PAD + kk + lkB) * 2);
            }
#pragma unroll
            for (int mt = 0; mt < 4; mt++)
#pragma unroll
                for (int nt = 0; nt < 4; nt++)
                    mma16816(acc[mt][nt][0], acc[mt][nt][1], acc[mt][nt][2], acc[mt][nt][3],
                             a[mt][0], a[mt][1], a[mt][2], a[mt][3], b[nt][0], b[nt][1]);
        }
        __syncthreads();
    }

#pragma unroll
    for (int mt = 0; mt < 4; mt++) {
        int mrow = m0 + wm * 64 + mt * 16 + (lane >> 2);
#pragma unroll
        for (int nt = 0; nt < 4; nt++) {
            int ncol = n0 + wn * 32 + nt * 8 + (lane & 3) * 2;
            if (ncol < N) {
                float b0 = bias[ncol], b1 = bias[ncol + 1];
                C[(size_t)mrow * N + ncol]     = acc[mt][nt][0] + b0;
                C[(size_t)mrow * N + ncol + 1] = acc[mt][nt][1] + b1;
                C[(size_t)(mrow + 8) * N + ncol]     = acc[mt][nt][2] + b0;
                C[(size_t)(mrow + 8) * N + ncol + 1] = acc[mt][nt][3] + b1;
            }
        }
    }
}

// ---------------- online row log-softmax (length n), in place ----------------
__global__ __launch_bounds__(512)
void logsoftmax_kernel(float* __restrict__ y, int n) {
    float* row = y + (size_t)blockIdx.x * n;
    __shared__ float sm[512], ss[512];
    int tid = threadIdx.x;
    float m = -INFINITY, s = 0.0f;
    for (int i = tid; i < n; i += 512) {
        float v = row[i];
        float nm = fmaxf(m, v);
        s = s * expf(m - nm) + expf(v - nm);
        m = nm;
    }
    sm[tid] = m; ss[tid] = s;
    __syncthreads();
    for (int o = 256; o; o >>= 1) {
        if (tid < o) {
            float m2 = sm[tid + o], s2 = ss[tid + o];
            float nm = fmaxf(sm[tid], m2);
            ss[tid] = ss[tid] * expf(sm[tid] - nm) + s2 * expf(m2 - nm);
            sm[tid] = nm;
        }
        __syncthreads();
    }
    float lse = sm[0] + logf(ss[0]);
    for (int i = tid; i < n; i += 512) row[i] = row[i] - lse;
}

// ---------------- launch ----------------
extern "C" void kernel_launch(void* const* d_in, const int* in_sizes, int n_in,
                              void* d_out, int out_size) {
    const int* loc  = (const int*)d_in[0];
    const int* tim  = (const int*)d_in[1];
    const int* clu  = (const int*)d_in[2];
    const int* hloc = (const int*)d_in[3];
    const int* hclu = (const int*)d_in[4];
    const int* htim = (const int*)d_in[5];
    const int* hcnt = (const int*)d_in[6];
    const int* uid  = (const int*)d_in[7];
    int e = (in_sizes[8] == 1) ? 9 : 8;
    const float* emb_loc    = (const float*)d_in[e + 0];
    const float* emb_tim    = (const float*)d_in[e + 1];
    const float* emb_clu    = (const float*)d_in[e + 2];
    const float* emb_uid    = (const float*)d_in[e + 3];
    const float* fc_attn_w  = (const float*)d_in[e + 4];
    const float* fc_attn_b  = (const float*)d_in[e + 5];
    const float* w_ih       = (const float*)d_in[e + 6];
    const float* w_hh       = (const float*)d_in[e + 7];
    const float* b_ih       = (const float*)d_in[e + 8];
    const float* b_hh       = (const float*)d_in[e + 9];
    const float* fc_final_w = (const float*)d_in[e + 10];
    const float* fc_final_b = (const float*)d_in[e + 11];
    float* out = (float*)d_out;

    float *px, *pgx, *phist, *pq, *pattn, *pctx;
    __nv_bfloat16 *pob, *pwb;
    cudaGetSymbolAddress((void**)&px, g_x);
    cudaGetSymbolAddress((void**)&pgx, g_gx);
    cudaGetSymbolAddress((void**)&phist, g_hist);
    cudaGetSymbolAddress((void**)&pq, g_q);
    cudaGetSymbolAddress((void**)&pattn, g_attn);
    cudaGetSymbolAddress((void**)&pctx, g_ctx);
    cudaGetSymbolAddress((void**)&pob, g_out_bf);
    cudaGetSymbolAddress((void**)&pwb, g_wf_bf);

    cudaFuncSetAttribute(gru_kernel,
                         cudaFuncAttributeMaxDynamicSharedMemorySize, GRU_SMEM);

    offsets_kernel<<<1, NG>>>(hcnt);                    // also resets barrier + helper counters
    build_x_kernel<<<SEQ, 256>>>(loc, clu, tim, emb_loc, emb_clu, emb_tim);

    // gx = x @ w_ih^T + b_ih                    (1024 x 1536, K=608)
    gemm_nt64<<<dim3(THID / 64, SEQ / 64), 128>>>(px, w_ih, pgx, SEQ, THID, INP, b_ih, 0);

    // GRU scan on CTAs 0..31; helpers do hist_feat -> hist GEMM -> weight conversion
    gru_kernel<<<GRU_GRID, GRU_THREADS, GRU_SMEM>>>(pgx, w_hh, b_hh, pq, fc_final_w,
                                                    hloc, hclu, htim, hcnt,
                                                    emb_loc, emb_clu, emb_tim,
                                                    fc_attn_w, fc_attn_b);

    // attn = softmax(q @ history^T)             (512 x 1024, K=512)
    gemm_nt64<<<dim3(NG / 64, TLEN / 64), 128>>>(pq, phist, pattn, TLEN, NG, HID, nullptr, 0);
    softmax_kernel<<<TLEN, 256>>>(pattn, NG);
    // context = attn @ history                  (512 x 512, K=1024)
    gemm_nn64<<<dim3(HID / 64, TLEN / 64), 128>>>(pattn, phist, pctx, TLEN, HID, NG);

    build_out_kernel<<<TLEN, 256>>>(emb_uid, uid);

    // y = out @ fc_final_w^T + b  (bf16 tensor cores, 512 x 50000, K=1088)
    gemm_final_bf16<<<dim3((NLOC + FG_BN - 1) / FG_BN, TLEN / FG_BM), 256>>>(pob, pwb, out, fc_final_b);
    logsoftmax_kernel<<<TLEN, 512>>>(out, NLOC);
}

// round 14
// speedup vs baseline: 1.4399x; 1.4399x over previous
#include <cuda_runtime.h>
#include <cuda_bf16.h>
#include <math.h>
#include <stdint.h>

// ---------------- problem constants ----------------
#define SEQ   1024
#define TLEN  512
#define NG    1024
#define HTOT  16384
#define D_LOC 512
#define D_TIM 32
#define D_CLU 64
#define D_UID 64
#define HID   512
#define INP   608            // D_LOC + D_CLU + D_TIM
#define THID  1536           // 3*HID
#define NLOC  50000
#define OUTD  1088           // 2*HID + D_UID

// GRU persistent kernel: CTAs 0..31 scan; CTAs 32..147 do hist pipeline + convert
#define GRU_CTAS 32
#define GRU_GRID 148
#define NHELP (GRU_GRID - GRU_CTAS)      // 116 helper CTAs
#define GRU_UPC  16                      // hidden units per CTA
#define GRU_ROWS 48                      // 3 * GRU_UPC w_hh rows per CTA
#define GRU_THREADS 512                  // 16 warps
#define GRU_RPW  3                       // rows per warp
#define GRU_SMEM (GRU_ROWS * HID * 4 + GRU_ROWS * 4 * 2)   // ws + rowsum + bias

// final GEMM (bf16 tensor) config
#define FG_BM 128
#define FG_BN 128
#define FG_BK 32
#define FG_PAD 40            // halves per smem row (80B stride, conflict-free LDSM)
#define FG_NK (OUTD / FG_BK) // 34

// ---------------- device scratch ----------------
__device__ float g_x[SEQ * INP];
__device__ float g_gx[SEQ * THID];
__device__ float g_hfeat[NG * INP];
__device__ float g_hist[NG * HID];
__device__ float g_hbuf[2][HID];
__device__ float g_q[TLEN * HID];
__device__ float g_attn[TLEN * NG];
__device__ float g_ctx[TLEN * HID];
__device__ __nv_bfloat16 g_out_bf[TLEN * OUTD];
__device__ __nv_bfloat16 g_wf_bf[(size_t)NLOC * OUTD];
__device__ int   g_off[NG];
// CRITICAL: scan barrier counters and helper counter on SEPARATE 128B L2 lines.
// (Round-13 regression root cause: they shared one line; 116 helper pollers
//  contended with the scan's per-step barrier RMWs.)
__device__ __align__(128) int g_bars[32];   // scan uses [0],[1]
__device__ __align__(128) int g_help[32];   // helpers use [0]

// ---------------- offsets (prefix sum of history_count) + barrier reset ----------------
__global__ void offsets_kernel(const int* __restrict__ cnt) {
    __shared__ int s[NG];
    int tid = threadIdx.x;
    s[tid] = cnt[tid];
    __syncthreads();
    for (int d = 1; d < NG; d <<= 1) {
        int v = (tid >= d) ? s[tid - d] : 0;
        __syncthreads();
        s[tid] += v;
        __syncthreads();
    }
    g_off[tid] = s[tid] - cnt[tid];
    if (tid < 2) g_bars[tid] = 0;
    if (tid == 2) g_help[0] = 0;
}

// ---------------- x features ----------------
__global__ void build_x_kernel(const int* __restrict__ loc, const int* __restrict__ clu,
                               const int* __restrict__ tim,
                               const float* __restrict__ emb_loc, const float* __restrict__ emb_clu,
                               const float* __restrict__ emb_tim) {
    int s = blockIdx.x;
    int tid = threadIdx.x;
    int l = loc[s], c = clu[s], t = tim[s];
    float* dst = g_x + (size_t)s * INP;
    for (int d = tid; d < D_LOC; d += blockDim.x) dst[d] = emb_loc[(size_t)l * D_LOC + d];
    for (int d = tid; d < D_CLU; d += blockDim.x) dst[D_LOC + d] = emb_clu[(size_t)c * D_CLU + d];
    for (int d = tid; d < D_TIM; d += blockDim.x) dst[D_LOC + D_CLU + d] = emb_tim[(size_t)t * D_TIM + d];
}

// ---------------- fp32 GEMM 64x64x16, C = A[M,K] * B[N,K]^T (+bias)(+tanh) ----------------
__global__ __launch_bounds__(128)
void gemm_nt64(const float* __restrict__ A, const float* __restrict__ B, float* __restrict__ C,
               int M, int N, int K, const float* __restrict__ bias, int act) {
    __shared__ float As[16][68];
    __shared__ float Bs[16][68];
    int m0 = blockIdx.y * 64, n0 = blockIdx.x * 64;
    int tid = threadIdx.x;
    int tx = tid & 15, ty = tid >> 4;
    float c[8][4];
#pragma unroll
    for (int i = 0; i < 8; i++)
#pragma unroll
        for (int j = 0; j < 4; j++) c[i][j] = 0.0f;

    for (int k0 = 0; k0 < K; k0 += 16) {
#pragma unroll
        for (int h = 0; h < 2; h++) {
            int cidx = tid + h * 128;
            int r = cidx >> 2, k4 = (cidx & 3) * 4;
            float4 av = *(const float4*)(A + (size_t)(m0 + r) * K + k0 + k4);
            As[k4 + 0][r] = av.x; As[k4 + 1][r] = av.y; As[k4 + 2][r] = av.z; As[k4 + 3][r] = av.w;
            float4 bv = *(const float4*)(B + (size_t)(n0 + r) * K + k0 + k4);
            Bs[k4 + 0][r] = bv.x; Bs[k4 + 1][r] = bv.y; Bs[k4 + 2][r] = bv.z; Bs[k4 + 3][r] = bv.w;
        }
        __syncthreads();
#pragma unroll
        for (int k = 0; k < 16; k++) {
            float a[8], b[4];
            *(float4*)&a[0] = *(const float4*)&As[k][ty * 8];
            *(float4*)&a[4] = *(const float4*)&As[k][ty * 8 + 4];
            *(float4*)&b[0] = *(const float4*)&Bs[k][tx * 4];
#pragma unroll
            for (int i = 0; i < 8; i++)
#pragma unroll
                for (int j = 0; j < 4; j++) c[i][j] = fmaf(a[i], b[j], c[i][j]);
        }
        __syncthreads();
    }
#pragma unroll
    for (int i = 0; i < 8; i++) {
        int m = m0 + ty * 8 + i;
#pragma unroll
        for (int j = 0; j < 4; j++) {
            int n = n0 + tx * 4 + j;
            float v = c[i][j];
            if (bias) v += bias[n];
            if (act == 1) v = tanhf(v);
            C[(size_t)m * N + n] = v;
        }
    }
}

// ---------------- fp32 GEMM 64x64x16, C = A[M,K] * B[K,N] ----------------
__global__ __launch_bounds__(128)
void gemm_nn64(const float* __restrict__ A, const float* __restrict__ B, float* __restrict__ C,
               int M, int N, int K) {
    __shared__ float As[16][68];
    __shared__ float Bs[16][68];
    int m0 = blockIdx.y * 64, n0 = blockIdx.x * 64;
    int tid = threadIdx.x;
    int tx = tid & 15, ty = tid >> 4;
    float c[8][4];
#pragma unroll
    for (int i = 0; i < 8; i++)
#pragma unroll
        for (int j = 0; j < 4; j++) c[i][j] = 0.0f;

    for (int k0 = 0; k0 < K; k0 += 16) {
#pragma unroll
        for (int h = 0; h < 2; h++) {
            int cidx = tid + h * 128;
            int r = cidx >> 2, k4 = (cidx & 3) * 4;
            float4 av = *(const float4*)(A + (size_t)(m0 + r) * K + k0 + k4);
            As[k4 + 0][r] = av.x; As[k4 + 1][r] = av.y; As[k4 + 2][r] = av.z; As[k4 + 3][r] = av.w;
            int kr = cidx >> 4, c4 = (cidx & 15) * 4;
            *(float4*)&Bs[kr][c4] = *(const float4*)(B + (size_t)(k0 + kr) * N + n0 + c4);
        }
        __syncthreads();
#pragma unroll
        for (int k = 0; k < 16; k++) {
            float a[8], b[4];
            *(float4*)&a[0] = *(const float4*)&As[k][ty * 8];
            *(float4*)&a[4] = *(const float4*)&As[k][ty * 8 + 4];
            *(float4*)&b[0] = *(const float4*)&Bs[k][tx * 4];
#pragma unroll
            for (int i = 0; i < 8; i++)
#pragma unroll
                for (int j = 0; j < 4; j++) c[i][j] = fmaf(a[i], b[j], c[i][j]);
        }
        __syncthreads();
    }
#pragma unroll
    for (int i = 0; i < 8; i++) {
        int m = m0 + ty * 8 + i;
#pragma unroll
        for (int j = 0; j < 4; j++)
            C[(size_t)m * N + n0 + tx * 4 + j] = c[i][j];
    }
}

// ---------------- persistent GRU scan + overlapped hist pipeline + weight conversion ----
// CTAs 0..31: exact round-12 scan (ping-pong barrier counters, isolated L2 line).
// CTAs 32..147 (helpers): hist_feat -> (gentle helper barrier) -> hist GEMM -> convert.
// Helper poll uses nanosleep backoff and its own 128B line: zero scan interference.
__global__ void __launch_bounds__(GRU_THREADS, 1)
gru_kernel(const float* __restrict__ gx, const float* __restrict__ w_hh,
           const float* __restrict__ b_hh, float* __restrict__ q,
           const float* __restrict__ wf,
           const int* __restrict__ hloc, const int* __restrict__ hclu,
           const int* __restrict__ htim, const int* __restrict__ hcnt,
           const float* __restrict__ emb_loc, const float* __restrict__ emb_clu,
           const float* __restrict__ emb_tim,
           const float* __restrict__ fc_attn_w, const float* __restrict__ fc_attn_b) {
    extern __shared__ float sm[];
    int b = blockIdx.x;
    int tid = threadIdx.x;

    if (b >= GRU_CTAS) {
        int hb = b - GRU_CTAS;                       // 0..115

        // ---- phase 1: history features ----
        for (int g = hb; g < NG; g += NHELP) {
            int off = g_off[g];
            int cnt = hcnt[g];
            float inv = 1.0f / (float)cnt;
            float* dst = g_hfeat + (size_t)g * INP;
            for (int d = tid; d < D_LOC; d += GRU_THREADS) {
                float s = 0.0f;
                for (int i = 0; i < cnt; i++)
                    s += emb_loc[(size_t)hloc[off + i] * D_LOC + d];
                dst[d] = s * inv;
            }
            for (int d = tid; d < D_CLU; d += GRU_THREADS) {
                float s = 0.0f;
                for (int i = 0; i < cnt; i++)
                    s += emb_clu[(size_t)hclu[off + i] * D_CLU + d];
                dst[D_LOC + d] = s * inv;
            }
            int t0 = htim[off];
            for (int d = tid; d < D_TIM; d += GRU_THREADS)
                dst[D_LOC + D_CLU + d] = emb_tim[(size_t)t0 * D_TIM + d];
        }

        // ---- helper-only barrier (own L2 line + nanosleep backoff) ----
        __threadfence();
        __syncthreads();
        if (tid == 0) {
            atomicAdd(&g_help[0], 1);
            volatile int* vh = &g_help[0];
            while (*vh < NHELP) { __nanosleep(128); }
            __threadfence();
        }
        __syncthreads();

        // ---- phase 2: hist GEMM tiles (64x64, K=608), loaders tid<256, compute tid<128 ----
        float (*As)[68] = (float (*)[68])sm;
        float (*Bs)[68] = (float (*)[68])(sm + 16 * 68);
        for (int tl = hb; tl < (HID / 64) * (NG / 64); tl += NHELP) {
            int n0 = (tl & 7) * 64;              // HID/64 = 8 tiles across
            int m0 = (tl >> 3) * 64;
            int tx = tid & 15, ty = (tid >> 4) & 7;
            float c[8][4];
#pragma unroll
            for (int i = 0; i < 8; i++)
#pragma unroll
                for (int j = 0; j < 4; j++) c[i][j] = 0.0f;
            for (int k0 = 0; k0 < INP; k0 += 16) {
                if (tid < 256) {
                    int r = tid >> 2, k4 = (tid & 3) * 4;
                    float4 av = *(const float4*)(g_hfeat + (size_t)(m0 + r) * INP + k0 + k4);
                    As[k4 + 0][r] = av.x; As[k4 + 1][r] = av.y; As[k4 + 2][r] = av.z; As[k4 + 3][r] = av.w;
                    float4 bv = *(const float4*)(fc_attn_w + (size_t)(n0 + r) * INP + k0 + k4);
                    Bs[k4 + 0][r] = bv.x; Bs[k4 + 1][r] = bv.y; Bs[k4 + 2][r] = bv.z; Bs[k4 + 3][r] = bv.w;
                }
                __syncthreads();
                if (tid < 128) {
#pragma unroll
                    for (int k = 0; k < 16; k++) {
                        float a[8], bb_[4];
                        *(float4*)&a[0] = *(const float4*)&As[k][ty * 8];
                        *(float4*)&a[4] = *(const float4*)&As[k][ty * 8 + 4];
                        *(float4*)&bb_[0] = *(const float4*)&Bs[k][tx * 4];
#pragma unroll
                        for (int i = 0; i < 8; i++)
#pragma unroll
                            for (int j = 0; j < 4; j++) c[i][j] = fmaf(a[i], bb_[j], c[i][j]);
                    }
                }
                __syncthreads();
            }
            if (tid < 128) {
#pragma unroll
                for (int i = 0; i < 8; i++) {
                    int m = m0 + ty * 8 + i;
#pragma unroll
                    for (int j = 0; j < 4; j++) {
                        int n = n0 + tx * 4 + j;
                        g_hist[(size_t)m * HID + n] = tanhf(c[i][j] + fc_attn_b[n]);
                    }
                }
            }
        }

        // ---- phase 3: fc_final_w conversion ----
        size_t n4 = (size_t)NLOC * OUTD / 4;
        const float4* src = (const float4*)wf;
        uint2* dst = (uint2*)g_wf_bf;
        size_t stride = (size_t)NHELP * GRU_THREADS;
        for (size_t i = (size_t)hb * GRU_THREADS + tid; i < n4; i += stride) {
            float4 v = src[i];
            __nv_bfloat162 lo = __floats2bfloat162_rn(v.x, v.y);
            __nv_bfloat162 hi = __floats2bfloat162_rn(v.z, v.w);
            uint2 o;
            o.x = *(unsigned int*)&lo;
            o.y = *(unsigned int*)&hi;
            dst[i] = o;
        }
        return;
    }

    // ---------------- scan CTAs (byte-identical to round 12) ----------------
    float* ws     = sm;                       // [48][512]
    float* rowsum = sm + GRU_ROWS * HID;      // [48]
    float* bb     = rowsum + GRU_ROWS;        // [48]
    int wid = tid >> 5, lane = tid & 31;
    int j0 = b * GRU_UPC;

    const float4* w4 = (const float4*)w_hh;
    float4* ws4 = (float4*)ws;
    for (int i4 = tid; i4 < GRU_ROWS * (HID / 4); i4 += GRU_THREADS) {
        int row = i4 >> 7, pos = i4 & 127;
        int g = row >> 4, u = row & 15;
        int grow = g * HID + j0 + u;
        ws4[i4] = w4[(size_t)grow * (HID / 4) + pos];
    }
    if (tid < GRU_ROWS) {
        int g = tid >> 4, u = tid & 15;
        bb[tid] = b_hh[g * HID + j0 + u];
    }
    __syncthreads();

    for (int t = 0; t < SEQ; t++) {
        const float* hr = g_hbuf[t & 1];

        float gxr = 0.f, gxz = 0.f, gxn = 0.f, hold = 0.f;
        if (tid < GRU_UPC) {
            const float* gxt = gx + (size_t)t * THID + j0 + tid;
            gxr = __ldcg(gxt);
            gxz = __ldcg(gxt + HID);
            gxn = __ldcg(gxt + 2 * HID);
            hold = (t == 0) ? 0.0f : __ldcg(&hr[j0 + tid]);
        }

        float4 hv[4];
#pragma unroll
        for (int c = 0; c < 4; c++)
            hv[c] = (t == 0) ? make_float4(0.f, 0.f, 0.f, 0.f)
                             : __ldcg((const float4*)&hr[lane * 4 + 128 * c]);

#pragma unroll
        for (int rr = 0; rr < GRU_RPW; rr++) {
            int row = wid * GRU_RPW + rr;
            const float4* wr = (const float4*)(ws + row * HID);
            float acc = 0.0f;
#pragma unroll
            for (int c = 0; c < 4; c++) {
                float4 wv = wr[lane + 32 * c];
                acc += wv.x * hv[c].x + wv.y * hv[c].y + wv.z * hv[c].z + wv.w * hv[c].w;
            }
#pragma unroll
            for (int o = 16; o; o >>= 1) acc += __shfl_xor_sync(0xffffffffu, acc, o);
            if (lane == 0) rowsum[row] = acc + bb[row];
        }
        __syncthreads();

        if (tid < GRU_UPC) {
            float r = 1.0f / (1.0f + expf(-(gxr + rowsum[tid])));
            float z = 1.0f / (1.0f + expf(-(gxz + rowsum[GRU_UPC + tid])));
            float n = tanhf(gxn + r * rowsum[2 * GRU_UPC + tid]);
            float hnew = (1.0f - z) * n + z * hold;
            __stcg(&g_hbuf[(t + 1) & 1][j0 + tid], hnew);
            if (t >= SEQ - TLEN)
                q[(size_t)(t - (SEQ - TLEN)) * HID + j0 + tid] = hnew;
            __threadfence();
        }
        __syncthreads();

        if (tid == 0) {
            int c = t & 1;
            atomicAdd(&g_bars[c], 1);
            volatile int* vb = &g_bars[c];
            int target = GRU_CTAS * ((t >> 1) + 1);
            while (*vb < target) { }
            __threadfence();
        }
        __syncthreads();
    }
}

// ---------------- row softmax (attn) ----------------
__global__ void softmax_kernel(float* __restrict__ a, int n) {
    float* row = a + (size_t)blockIdx.x * n;
    __shared__ float red[256];
    int tid = threadIdx.x;
    float m = -INFINITY;
    for (int i = tid; i < n; i += 256) m = fmaxf(m, row[i]);
    red[tid] = m; __syncthreads();
    for (int o = 128; o; o >>= 1) { if (tid < o) red[tid] = fmaxf(red[tid], red[tid + o]); __syncthreads(); }
    m = red[0]; __syncthreads();
    float s = 0.0f;
    for (int i = tid; i < n; i += 256) s += expf(row[i] - m);
    red[tid] = s; __syncthreads();
    for (int o = 128; o; o >>= 1) { if (tid < o) red[tid] += red[tid + o]; __syncthreads(); }
    float inv = 1.0f / red[0];
    for (int i = tid; i < n; i += 256) row[i] = expf(row[i] - m) * inv;
}

// ---------------- concat(q, context, uid_emb) -> bf16 ----------------
__global__ void build_out_kernel(const float* __restrict__ emb_uid, const int* __restrict__ uid) {
    int t = blockIdx.x;
    int tid = threadIdx.x;
    int u = uid[0];
    __nv_bfloat16* dst = g_out_bf + (size_t)t * OUTD;
    for (int d = tid; d < HID; d += blockDim.x) dst[d] = __float2bfloat16(g_q[(size_t)t * HID + d]);
    for (int d = tid; d < HID; d += blockDim.x) dst[HID + d] = __float2bfloat16(g_ctx[(size_t)t * HID + d]);
    for (int d = tid; d < D_UID; d += blockDim.x) dst[2 * HID + d] = __float2bfloat16(emb_uid[(size_t)u * D_UID + d]);
}

// ---------------- bf16 tensor-core final GEMM: C[512,50000] = A @ B^T + bias ----------------
__device__ __forceinline__ void ldsm_x4(unsigned& a0, unsigned& a1, unsigned& a2, unsigned& a3, uint32_t addr) {
    asm volatile("ldmatrix.sync.aligned.m8n8.x4.shared.b16 {%0,%1,%2,%3}, [%4];"
                 : "=r"(a0), "=r"(a1), "=r"(a2), "=r"(a3) : "r"(addr));
}
__device__ __forceinline__ void ldsm_x2(unsigned& b0, unsigned& b1, uint32_t addr) {
    asm volatile("ldmatrix.sync.aligned.m8n8.x2.shared.b16 {%0,%1}, [%2];"
                 : "=r"(b0), "=r"(b1) : "r"(addr));
}
__device__ __forceinline__ void mma16816(float& c0, float& c1, float& c2, float& c3,
                                         unsigned a0, unsigned a1, unsigned a2, unsigned a3,
                                         unsigned b0, unsigned b1) {
    asm volatile("mma.sync.aligned.m16n8k16.row.col.f32.bf16.bf16.f32 "
                 "{%0,%1,%2,%3}, {%4,%5,%6,%7}, {%8,%9}, {%0,%1,%2,%3};"
                 : "+f"(c0), "+f"(c1), "+f"(c2), "+f"(c3)
                 : "r"(a0), "r"(a1), "r"(a2), "r"(a3), "r"(b0), "r"(b1));
}
__device__ __forceinline__ void cp16(uint32_t saddr, const void* gaddr) {
    asm volatile("cp.async.cg.shared.global [%0], [%1], 16;" :: "r"(saddr), "l"(gaddr));
}
__device__ __forceinline__ void cp16_pred(uint32_t saddr, const void* gaddr, bool p) {
    int sz = p ? 16 : 0;
    asm volatile("cp.async.cg.shared.global [%0], [%1], 16, %2;" :: "r"(saddr), "l"(gaddr), "r"(sz));
}

__global__ __launch_bounds__(256)
void gemm_final_bf16(const __nv_bfloat16* __restrict__ A, const __nv_bfloat16* __restrict__ B,
                     float* __restrict__ C, const float* __restrict__ bias) {
    __shared__ __nv_bfloat16 As[2][FG_BM * FG_PAD];
    __shared__ __nv_bfloat16 Bs[2][FG_BN * FG_PAD];
    const int K = OUTD, N = NLOC;
    int n0 = blockIdx.x * FG_BN, m0 = blockIdx.y * FG_BM;
    int tid = threadIdx.x, lane = tid & 31, warp = tid >> 5;
    int wm = warp >> 2, wn = warp & 3;

    float acc[4][4][4];
#pragma unroll
    for (int mt = 0; mt < 4; mt++)
#pragma unroll
        for (int nt = 0; nt < 4; nt++)
#pragma unroll
            for (int i = 0; i < 4; i++) acc[mt][nt][i] = 0.0f;

    uint32_t as0 = (uint32_t)__cvta_generic_to_shared(&As[0][0]);
    uint32_t as1 = (uint32_t)__cvta_generic_to_shared(&As[1][0]);
    uint32_t bs0 = (uint32_t)__cvta_generic_to_shared(&Bs[0][0]);
    uint32_t bs1 = (uint32_t)__cvta_generic_to_shared(&Bs[1][0]);

    int lrow = tid >> 2;
    int lcol = (tid & 3) * 8;

    auto load_tile = [&](int buf, int kt) {
        int k0 = kt * FG_BK;
        uint32_t ab = buf ? as1 : as0;
        uint32_t bb_ = buf ? bs1 : bs0;
#pragma unroll
        for (int h = 0; h < 2; h++) {
            int r = lrow + h * 64;
            cp16(ab + (r * FG_PAD + lcol) * 2, A + (size_t)(m0 + r) * K + k0 + lcol);
            int n = n0 + r;
            bool ok = n < N;
            const __nv_bfloat16* src = B + (size_t)(ok ? n : 0) * K + k0 + lcol;
            cp16_pred(bb_ + (r * FG_PAD + lcol) * 2, src, ok);
        }
    };

    load_tile(0, 0);
    asm volatile("cp.async.commit_group;");

    int l15 = lane & 15;
    int lkA = (lane >> 4) * 8;
    int l7 = lane & 7;
    int lkB = ((lane >> 3) & 1) * 8;

    for (int kt = 0; kt < FG_NK; kt++) {
        if (kt + 1 < FG_NK) {
            load_tile((kt + 1) & 1, kt + 1);
            asm volatile("cp.async.commit_group;");
            asm volatile("cp.async.wait_group 1;");
        } else {
            asm volatile("cp.async.wait_group 0;");
        }
        __syncthreads();
        int buf = kt & 1;
        uint32_t ab = buf ? as1 : as0;
        uint32_t bb_ = buf ? bs1 : bs0;
#pragma unroll
        for (int kk = 0; kk < FG_BK; kk += 16) {
            unsigned a[4][4], b[4][2];
#pragma unroll
            for (int mt = 0; mt < 4; mt++) {
                int row = wm * 64 + mt * 16 + l15;
                ldsm_x4(a[mt][0], a[mt][1], a[mt][2], a[mt][3],
                        ab + (row * FG_PAD + kk + lkA) * 2);
            }
#pragma unroll
            for (int nt = 0; nt < 4; nt++) {
                int row = wn * 32 + nt * 8 + l7;
                ldsm_x2(b[nt][0], b[nt][1],
                        bb_ + (row * FG_PAD + kk + lkB) * 2);
            }
#pragma unroll
            for (int mt = 0; mt < 4; mt++)
#pragma unroll
                for (int nt = 0; nt < 4; nt++)
                    mma16816(acc[mt][nt][0], acc[mt][nt][1], acc[mt][nt][2], acc[mt][nt][3],
                             a[mt][0], a[mt][1], a[mt][2], a[mt][3], b[nt][0], b[nt][1]);
        }
        __syncthreads();
    }

#pragma unroll
    for (int mt = 0; mt < 4; mt++) {
        int mrow = m0 + wm * 64 + mt * 16 + (lane >> 2);
#pragma unroll
        for (int nt = 0; nt < 4; nt++) {
            int ncol = n0 + wn * 32 + nt * 8 + (lane & 3) * 2;
            if (ncol < N) {
                float b0 = bias[ncol], b1 = bias[ncol + 1];
                C[(size_t)mrow * N + ncol]     = acc[mt][nt][0] + b0;
                C[(size_t)mrow * N + ncol + 1] = acc[mt][nt][1] + b1;
                C[(size_t)(mrow + 8) * N + ncol]     = acc[mt][nt][2] + b0;
                C[(size_t)(mrow + 8) * N + ncol + 1] = acc[mt][nt][3] + b1;
            }
        }
    }
}

// ---------------- online row log-softmax (length n), in place ----------------
__global__ __launch_bounds__(512)
void logsoftmax_kernel(float* __restrict__ y, int n) {
    float* row = y + (size_t)blockIdx.x * n;
    __shared__ float sm[512], ss[512];
    int tid = threadIdx.x;
    float m = -INFINITY, s = 0.0f;
    for (int i = tid; i < n; i += 512) {
        float v = row[i];
        float nm = fmaxf(m, v);
        s = s * expf(m - nm) + expf(v - nm);
        m = nm;
    }
    sm[tid] = m; ss[tid] = s;
    __syncthreads();
    for (int o = 256; o; o >>= 1) {
        if (tid < o) {
            float m2 = sm[tid + o], s2 = ss[tid + o];
            float nm = fmaxf(sm[tid], m2);
            ss[tid] = ss[tid] * expf(sm[tid] - nm) + s2 * expf(m2 - nm);
            sm[tid] = nm;
        }
        __syncthreads();
    }
    float lse = sm[0] + logf(ss[0]);
    for (int i = tid; i < n; i += 512) row[i] = row[i] - lse;
}

// ---------------- launch ----------------
extern "C" void kernel_launch(void* const* d_in, const int* in_sizes, int n_in,
                              void* d_out, int out_size) {
    const int* loc  = (const int*)d_in[0];
    const int* tim  = (const int*)d_in[1];
    const int* clu  = (const int*)d_in[2];
    const int* hloc = (const int*)d_in[3];
    const int* hclu = (const int*)d_in[4];
    const int* htim = (const int*)d_in[5];
    const int* hcnt = (const int*)d_in[6];
    const int* uid  = (const int*)d_in[7];
    int e = (in_sizes[8] == 1) ? 9 : 8;
    const float* emb_loc    = (const float*)d_in[e + 0];
    const float* emb_tim    = (const float*)d_in[e + 1];
    const float* emb_clu    = (const float*)d_in[e + 2];
    const float* emb_uid    = (const float*)d_in[e + 3];
    const float* fc_attn_w  = (const float*)d_in[e + 4];
    const float* fc_attn_b  = (const float*)d_in[e + 5];
    const float* w_ih       = (const float*)d_in[e + 6];
    const float* w_hh       = (const float*)d_in[e + 7];
    const float* b_ih       = (const float*)d_in[e + 8];
    const float* b_hh       = (const float*)d_in[e + 9];
    const float* fc_final_w = (const float*)d_in[e + 10];
    const float* fc_final_b = (const float*)d_in[e + 11];
    float* out = (float*)d_out;

    float *px, *pgx, *phist, *pq, *pattn, *pctx;
    __nv_bfloat16 *pob, *pwb;
    cudaGetSymbolAddress((void**)&px, g_x);
    cudaGetSymbolAddress((void**)&pgx, g_gx);
    cudaGetSymbolAddress((void**)&phist, g_hist);
    cudaGetSymbolAddress((void**)&pq, g_q);
    cudaGetSymbolAddress((void**)&pattn, g_attn);
    cudaGetSymbolAddress((void**)&pctx, g_ctx);
    cudaGetSymbolAddress((void**)&pob, g_out_bf);
    cudaGetSymbolAddress((void**)&pwb, g_wf_bf);

    cudaFuncSetAttribute(gru_kernel,
                         cudaFuncAttributeMaxDynamicSharedMemorySize, GRU_SMEM);

    offsets_kernel<<<1, NG>>>(hcnt);                    // also resets barrier + helper counters
    build_x_kernel<<<SEQ, 256>>>(loc, clu, tim, emb_loc, emb_clu, emb_tim);

    // gx = x @ w_ih^T + b_ih                    (1024 x 1536, K=608)
    gemm_nt64<<<dim3(THID / 64, SEQ / 64), 128>>>(px, w_ih, pgx, SEQ, THID, INP, b_ih, 0);

    // GRU scan on CTAs 0..31; helpers do hist_feat -> hist GEMM -> weight conversion
    gru_kernel<<<GRU_GRID, GRU_THREADS, GRU_SMEM>>>(pgx, w_hh, b_hh, pq, fc_final_w,
                                                    hloc, hclu, htim, hcnt,
                                                    emb_loc, emb_clu, emb_tim,
                                                    fc_attn_w, fc_attn_b);

    // attn = softmax(q @ history^T)             (512 x 1024, K=512)
    gemm_nt64<<<dim3(NG / 64, TLEN / 64), 128>>>(pq, phist, pattn, TLEN, NG, HID, nullptr, 0);
    softmax_kernel<<<TLEN, 256>>>(pattn, NG);
    // context = attn @ history                  (512 x 512, K=1024)
    gemm_nn64<<<dim3(HID / 64, TLEN / 64), 128>>>(pattn, phist, pctx, TLEN, HID, NG);

    build_out_kernel<<<TLEN, 256>>>(emb_uid, uid);

    // y = out @ fc_final_w^T + b  (bf16 tensor cores, 512 x 50000, K=1088)
    gemm_final_bf16<<<dim3((NLOC + FG_BN - 1) / FG_BN, TLEN / FG_BM), 256>>>(pob, pwb, out, fc_final_b);
    logsoftmax_kernel<<<TLEN, 512>>>(out, NLOC);
}